// round 15
// baseline (speedup 1.0000x reference)
#include <cuda_runtime.h>
#include <cuda_fp16.h>
#include <cstdint>

#define NN   100000
#define EE   1000000
#define RR   4
#define GG   256
#define DHH  128
#define NCC  10
#define KK   (RR*DHH)   // 512
#define SB   98         // ceil(NN/1024)

// ---------------- scratch ----------------
__device__ __half    g_f16[(size_t)NN*DHH];
__device__ __half    g_h0h[(size_t)NN*DHH];
__device__ __half    g_h1h[(size_t)NN*DHH];
__device__ __half    g_aggh[(size_t)(NN+256)*KK];    // pad rows stay zero (never written)
__device__ unsigned  g_wt[3*DHH*256];                // per-layer W^T pair-packed half2
__device__ int       g_deg_out[RR*NN];
__device__ int       g_deg_in [RR*NN];
__device__ float     g_rno[RR*NN];
__device__ float     g_rni[RR*NN];
__device__ int       g_rowptr[RR*(NN+1)];
__device__ int       g_cursor[RR*NN];
__device__ unsigned  g_pcsr[(size_t)RR*EE];          // packed (src<<15)|(fp16 rno sans sign)
__device__ int       g_bsum[RR*SB];

// ---------------- conversions + degree zeroing (one kernel, runs first) ----------------
__global__ void conv_fw_k(const float* __restrict__ f, const float* __restrict__ W0,
                          const float* __restrict__ Wl) {
    int i = blockIdx.x * blockDim.x + threadIdx.x;
    if (i < NN*DHH/2) {
        float2 v = ((const float2*)f)[i];
        ((__half2*)g_f16)[i] = __floats2half2_rn(v.x, v.y);
    }
    if (i < 3*DHH*256) {
        int l = i / (DHH*256);
        int rem = i - l*DHH*256;
        int col = rem >> 8;
        int p = rem & 255;
        const float* src = (l == 0) ? W0 : Wl + (size_t)(l-1)*KK*DHH;
        __half2 hv = __floats2half2_rn(src[(size_t)(2*p)*DHH + col],
                                       src[(size_t)(2*p+1)*DHH + col]);
        g_wt[i] = *reinterpret_cast<unsigned*>(&hv);
    }
    if (i < RR*NN) { g_deg_out[i] = 0; g_deg_in[i] = 0; }
}

// ---------------- preprocessing ----------------
__global__ void count_deg_k(const int* __restrict__ edges) {
    int i = blockIdx.x * blockDim.x + threadIdx.x;
    if (i >= RR*EE/4) return;
    int r = i / (EE/4), q = i - r*(EE/4);
    int4 s = *(const int4*)(edges + (size_t)r*2*EE + q*4);
    int4 d = *(const int4*)(edges + (size_t)r*2*EE + EE + q*4);
    int* dout = g_deg_out + r*NN;
    int* din  = g_deg_in  + r*NN;
    atomicAdd(&dout[s.x], 1); atomicAdd(&dout[s.y], 1);
    atomicAdd(&dout[s.z], 1); atomicAdd(&dout[s.w], 1);
    atomicAdd(&din[d.x], 1);  atomicAdd(&din[d.y], 1);
    atomicAdd(&din[d.z], 1);  atomicAdd(&din[d.w], 1);
}

// block-local exclusive scan via warp shuffles; emits per-block sums
__global__ void scan1_k() {
    __shared__ int wsum[32];
    int r = blockIdx.y, b = blockIdx.x, t = threadIdx.x;
    int wp = t >> 5, lane = t & 31;
    int i = b * 1024 + t;
    int v = (i < NN) ? g_deg_in[r*NN + i] : 0;

    int s = v;
    #pragma unroll
    for (int o = 1; o < 32; o <<= 1) {
        int x = __shfl_up_sync(0xFFFFFFFFu, s, o);
        if (lane >= o) s += x;
    }
    if (lane == 31) wsum[wp] = s;
    __syncthreads();
    if (wp == 0) {
        int ws = wsum[lane];
        #pragma unroll
        for (int o = 1; o < 32; o <<= 1) {
            int x = __shfl_up_sync(0xFFFFFFFFu, ws, o);
            if (lane >= o) ws += x;
        }
        wsum[lane] = ws;
    }
    __syncthreads();

    int base = (wp > 0) ? wsum[wp - 1] : 0;
    int excl = base + s - v;
    if (i < NN) g_rowptr[r*(NN+1) + i] = excl;
    if (t == 1023) g_bsum[r*SB + b] = wsum[31];
}

// scan3 with inlined block-prefix: each block covers 256 consecutive linear
// indices -> at most 2 distinct (r, bsum-block) offsets; warps 0/1 compute
// them via masked warp reduction over <=98 bsum values.
__global__ void scan3_k() {
    __shared__ int pref[2];     // prefix for bsum-block of first/last element
    int blk0 = blockIdx.x * 256;
    int wp = threadIdx.x >> 5, lane = threadIdx.x & 31;

    if (wp < 2) {
        int li = blk0 + wp*255;               // first / last linear index of block
        int r = li / NN, n = li - r*NN;
        if (li < RR*NN) {
            int bb = n >> 10;                 // bsum block to take prefix of
            int acc = 0;
            for (int c = lane; c < SB; c += 32)
                if (c < bb) acc += g_bsum[r*SB + c];
            #pragma unroll
            for (int o = 16; o > 0; o >>= 1)
                acc += __shfl_down_sync(0xFFFFFFFFu, acc, o);
            if (lane == 0) pref[wp] = acc;
        }
    }
    // warp 2 of the first RR blocks: per-relation totals -> rowptr[NN]
    if (wp == 2 && blockIdx.x < RR) {
        int r = blockIdx.x;
        int acc = 0;
        for (int c = lane; c < SB; c += 32) acc += g_bsum[r*SB + c];
        #pragma unroll
        for (int o = 16; o > 0; o >>= 1)
            acc += __shfl_down_sync(0xFFFFFFFFu, acc, o);
        if (lane == 0) g_rowptr[r*(NN+1) + NN] = acc;
    }
    __syncthreads();

    int i = blk0 + threadIdx.x;
    if (i >= RR*NN) return;
    int r = i / NN, n = i - r*NN;
    int r0 = blk0 / NN, n0 = blk0 - r0*NN;
    int off = (r == r0 && (n >> 10) == (n0 >> 10)) ? pref[0] : pref[1];
    int v = g_rowptr[r*(NN+1) + n] + off;
    g_rowptr[r*(NN+1) + n] = v;
    g_cursor[r*NN + n] = v;
    g_rno[i] = rsqrtf(fmaxf((float)g_deg_out[i], 1.0f));
    g_rni[i] = rsqrtf(fmaxf((float)g_deg_in [i], 1.0f));
}

__global__ void fill_k(const int* __restrict__ edges) {
    int i = blockIdx.x * blockDim.x + threadIdx.x;
    if (i >= RR*EE/4) return;
    int r = i / (EE/4), q = i - r*(EE/4);
    int4 s4 = *(const int4*)(edges + (size_t)r*2*EE + q*4);
    int4 d4 = *(const int4*)(edges + (size_t)r*2*EE + EE + q*4);
    const float* rno = g_rno + r*NN;
    int* cur = g_cursor + r*NN;
    unsigned* pc = g_pcsr + (size_t)r*EE;
    #pragma unroll
    for (int j = 0; j < 4; j++) {
        int src = (j == 0) ? s4.x : (j == 1) ? s4.y : (j == 2) ? s4.z : s4.w;
        int dst = (j == 0) ? d4.x : (j == 1) ? d4.y : (j == 2) ? d4.z : d4.w;
        float w = rno[src];
        unsigned short hb = __half_as_ushort(__float2half_rn(w));  // sign bit = 0
        unsigned ent = ((unsigned)src << 15) | (unsigned)(hb & 0x7FFF);
        int pos = atomicAdd(&cur[dst], 1);
        pc[pos] = ent;
    }
}

// ---------------- aggregation (proven): warp per (r,dst), 2 edges split ----------------
__global__ void __launch_bounds__(256) agg_k(int sel) {
    const __half* hin = (sel == 0) ? g_f16 : (sel == 1 ? g_h0h : g_h1h);
    int w = (blockIdx.x * blockDim.x + threadIdx.x) >> 5;
    if (w >= RR*NN) return;
    int lane = threadIdx.x & 31;
    int half = lane >> 4;
    int hl   = lane & 15;
    int r = w / NN, n = w - r*NN;
    int e0 = g_rowptr[r*(NN+1) + n];
    int e1 = g_rowptr[r*(NN+1) + n + 1];
    const unsigned* pc = g_pcsr + (size_t)r*EE;

    float a0=0.f,a1=0.f,a2=0.f,a3=0.f,a4=0.f,a5=0.f,a6=0.f,a7=0.f;
    for (int e = e0 + half; e < e1; e += 2) {
        unsigned ent = __ldg(pc + e);
        int s = ent >> 15;
        float wgt = __half2float(__ushort_as_half((unsigned short)(ent & 0x7FFF)));
        uint4 v = __ldg((const uint4*)(hin + (size_t)s*DHH) + hl);
        float2 f0 = __half22float2(*reinterpret_cast<__half2*>(&v.x));
        float2 f1 = __half22float2(*reinterpret_cast<__half2*>(&v.y));
        float2 f2 = __half22float2(*reinterpret_cast<__half2*>(&v.z));
        float2 f3 = __half22float2(*reinterpret_cast<__half2*>(&v.w));
        a0 = fmaf(wgt, f0.x, a0); a1 = fmaf(wgt, f0.y, a1);
        a2 = fmaf(wgt, f1.x, a2); a3 = fmaf(wgt, f1.y, a3);
        a4 = fmaf(wgt, f2.x, a4); a5 = fmaf(wgt, f2.y, a5);
        a6 = fmaf(wgt, f3.x, a6); a7 = fmaf(wgt, f3.y, a7);
    }
    a0 += __shfl_down_sync(0xFFFFFFFFu, a0, 16);
    a1 += __shfl_down_sync(0xFFFFFFFFu, a1, 16);
    a2 += __shfl_down_sync(0xFFFFFFFFu, a2, 16);
    a3 += __shfl_down_sync(0xFFFFFFFFu, a3, 16);
    a4 += __shfl_down_sync(0xFFFFFFFFu, a4, 16);
    a5 += __shfl_down_sync(0xFFFFFFFFu, a5, 16);
    a6 += __shfl_down_sync(0xFFFFFFFFu, a6, 16);
    a7 += __shfl_down_sync(0xFFFFFFFFu, a7, 16);

    if (half == 0) {
        float ri = g_rni[r*NN + n];
        __half2 p0 = __floats2half2_rn(ri*a0, ri*a1);
        __half2 p1 = __floats2half2_rn(ri*a2, ri*a3);
        __half2 p2 = __floats2half2_rn(ri*a4, ri*a5);
        __half2 p3 = __floats2half2_rn(ri*a6, ri*a7);
        uint4 o;
        o.x = *reinterpret_cast<unsigned*>(&p0);
        o.y = *reinterpret_cast<unsigned*>(&p1);
        o.z = *reinterpret_cast<unsigned*>(&p2);
        o.w = *reinterpret_cast<unsigned*>(&p3);
        *((uint4*)(g_aggh + (size_t)n*KK + r*DHH) + hl) = o;
    }
}

// ---------------- fp16 tensor-core GEMM: BM=256, cp.async 2-group pipeline ----------------
__device__ __forceinline__ void mma_f16(float* c, const unsigned* a, const unsigned* b) {
    asm volatile(
        "mma.sync.aligned.m16n8k16.row.col.f32.f16.f16.f32 "
        "{%0,%1,%2,%3}, {%4,%5,%6,%7}, {%8,%9}, {%0,%1,%2,%3};"
        : "+f"(c[0]), "+f"(c[1]), "+f"(c[2]), "+f"(c[3])
        : "r"(a[0]), "r"(a[1]), "r"(a[2]), "r"(a[3]), "r"(b[0]), "r"(b[1]));
}

// BM=256, BN=128, BK=16, 512 threads, 16 warps 4(m)x4(n), warp tile 64x32
__global__ void __launch_bounds__(512) gemm_tc_k(int layer, const float* __restrict__ Bv,
                                                 int outsel) {
    __shared__ unsigned As[2][256][12];
    __shared__ unsigned Bs[2][128][12];

    __half* O = (outsel == 0) ? g_h0h : g_h1h;
    const __half* A = g_aggh;
    const unsigned* Wt = g_wt + (size_t)layer*DHH*256;

    int tid = threadIdx.x;
    int rb = blockIdx.x * 256;
    int wid = tid >> 5, lane = tid & 31;
    int wm = wid & 3, wn = wid >> 2;
    int g = lane >> 2, t = lane & 3;

    float acc[4][4][4];
    #pragma unroll
    for (int mt = 0; mt < 4; mt++)
        #pragma unroll
        for (int nt = 0; nt < 4; nt++)
            #pragma unroll
            for (int j = 0; j < 4; j++) acc[mt][nt][j] = 0.f;

    auto issue = [&](int kt, int buf) {
        // A: 1024 8B-units, 2 per thread (pad rows of g_aggh are zero)
        #pragma unroll
        for (int p = 0; p < 2; p++) {
            int idx = tid + p*512;
            int row = idx >> 2, q = idx & 3;
            const __half* ga = A + (size_t)(rb + row)*KK + kt*16 + q*4;
            unsigned sA = (unsigned)__cvta_generic_to_shared(&As[buf][row][2*q]);
            asm volatile("cp.async.ca.shared.global [%0], [%1], 8;" :: "r"(sA), "l"(ga));
        }
        // B: 512 8B-units, 1 per thread
        {
            int row = tid >> 2, q = tid & 3;
            const unsigned* gb = Wt + (size_t)row*256 + kt*8 + q*2;
            unsigned sB = (unsigned)__cvta_generic_to_shared(&Bs[buf][row][2*q]);
            asm volatile("cp.async.ca.shared.global [%0], [%1], 8;" :: "r"(sB), "l"(gb));
        }
        asm volatile("cp.async.commit_group;");
    };

    issue(0, 0);

    for (int kt = 0; kt < 32; kt++) {
        int cur = kt & 1;
        if (kt < 31) {
            issue(kt + 1, cur ^ 1);                    // overlaps compute(kt)
            asm volatile("cp.async.wait_group 1;");    // group kt done; kt+1 in flight
        } else {
            asm volatile("cp.async.wait_group 0;");
        }
        __syncthreads();

        unsigned af[4][4], bf[4][2];
        #pragma unroll
        for (int mt = 0; mt < 4; mt++) {
            int r0 = wm*64 + mt*16 + g;
            af[mt][0] = As[cur][r0    ][t];
            af[mt][1] = As[cur][r0 + 8][t];
            af[mt][2] = As[cur][r0    ][t + 4];
            af[mt][3] = As[cur][r0 + 8][t + 4];
        }
        #pragma unroll
        for (int nt = 0; nt < 4; nt++) {
            int c0 = wn*32 + nt*8 + g;
            bf[nt][0] = Bs[cur][c0][t];
            bf[nt][1] = Bs[cur][c0][t + 4];
        }
        #pragma unroll
        for (int mt = 0; mt < 4; mt++)
            #pragma unroll
            for (int nt = 0; nt < 4; nt++)
                mma_f16(acc[mt][nt], af[mt], bf[nt]);

        __syncthreads();   // frees buf cur for issue(kt+2)
    }

    float bias[4][2];
    #pragma unroll
    for (int nt = 0; nt < 4; nt++) {
        int c0 = wn*32 + nt*8 + 2*t;
        #pragma unroll
        for (int j = 0; j < 2; j++) {
            float s = 0.f;
            #pragma unroll
            for (int r = 0; r < RR; r++) s += Bv[r*DHH + c0 + j];
            bias[nt][j] = s;
        }
    }
    #pragma unroll
    for (int mt = 0; mt < 4; mt++) {
        int r0 = rb + wm*64 + mt*16 + g;
        #pragma unroll
        for (int nt = 0; nt < 4; nt++) {
            int c = wn*32 + nt*8 + 2*t;
            if (r0 < NN) {
                *(__half2*)(O + (size_t)r0*DHH + c) =
                    __floats2half2_rn(fmaxf(acc[mt][nt][0] + bias[nt][0], 0.f),
                                      fmaxf(acc[mt][nt][1] + bias[nt][1], 0.f));
            }
            if (r0 + 8 < NN) {
                *(__half2*)(O + (size_t)(r0+8)*DHH + c) =
                    __floats2half2_rn(fmaxf(acc[mt][nt][2] + bias[nt][0], 0.f),
                                      fmaxf(acc[mt][nt][3] + bias[nt][1], 0.f));
            }
        }
    }
}

// ---------------- pooling + classifier (binary-search bounds, fused) ----------------
__global__ void poolcls_k(const int* __restrict__ gid, const float* __restrict__ Wc,
                          const float* __restrict__ bc, float* __restrict__ out) {
    __shared__ float sh[3*DHH];
    __shared__ float pooled[DHH];
    __shared__ int ab[2];
    int g = blockIdx.x;
    if (threadIdx.x < 2) {
        int target = g + threadIdx.x;
        int lo = 0, hi = NN;
        while (lo < hi) {
            int mid = (lo + hi) >> 1;
            if (gid[mid] < target) lo = mid + 1; else hi = mid;
        }
        ab[threadIdx.x] = lo;
    }
    __syncthreads();
    int a = ab[0], b = ab[1];
    int j  = threadIdx.x & 127;
    int rl = threadIdx.x >> 7;
    float s = 0.f;
    for (int n = a + rl; n < b; n += 4)
        s += __half2float(g_h0h[(size_t)n*DHH + j]);
    if (rl > 0) sh[(rl-1)*DHH + j] = s;
    __syncthreads();
    if (rl == 0) {
        s += sh[j] + sh[DHH + j] + sh[2*DHH + j];
        float c = fmaxf((float)(b - a), 1.0f);
        pooled[j] = s / c;
    }
    __syncthreads();
    int wid = threadIdx.x >> 5, lane = threadIdx.x & 31;
    if (wid < NCC) {
        float acc = 0.f;
        #pragma unroll
        for (int k = lane; k < DHH; k += 32)
            acc = fmaf(pooled[k], Wc[k*NCC + wid], acc);
        #pragma unroll
        for (int o = 16; o > 0; o >>= 1)
            acc += __shfl_down_sync(0xFFFFFFFFu, acc, o);
        if (lane == 0) out[g*NCC + wid] = acc + bc[wid];
    }
}

// ---------------- launch ----------------
extern "C" void kernel_launch(void* const* d_in, const int* in_sizes, int n_in,
                              void* d_out, int out_size) {
    const float* features = (const float*)d_in[0];
    const int*   edges    = (const int*)  d_in[1];
    const int*   gids     = (const int*)  d_in[2];
    const float* W0       = (const float*)d_in[3];
    const float* b0       = (const float*)d_in[4];
    const float* Wl       = (const float*)d_in[5];
    const float* bl       = (const float*)d_in[6];
    const float* Wc       = (const float*)d_in[7];
    const float* bc       = (const float*)d_in[8];
    float* out = (float*)d_out;

    conv_fw_k  <<<(NN*DHH/2 + 255)/256, 256>>>(features, W0, Wl);   // also zeros degrees
    count_deg_k<<<(RR*EE/4 + 255)/256, 256>>>(edges);
    scan1_k    <<<dim3(SB, RR), 1024>>>();
    scan3_k    <<<(RR*NN + 255)/256, 256>>>();
    fill_k     <<<(RR*EE/4 + 255)/256, 256>>>(edges);

    const int AGG_BLOCKS  = (RR*NN*32 + 255)/256;
    const int GEMM_BLOCKS = (NN + 255)/256;

    agg_k    <<<AGG_BLOCKS, 256>>>(0);
    gemm_tc_k<<<GEMM_BLOCKS, 512>>>(0, b0, 0);
    agg_k    <<<AGG_BLOCKS, 256>>>(1);
    gemm_tc_k<<<GEMM_BLOCKS, 512>>>(1, bl, 1);
    agg_k    <<<AGG_BLOCKS, 256>>>(2);
    gemm_tc_k<<<GEMM_BLOCKS, 512>>>(2, bl + RR*DHH, 0);

    poolcls_k<<<GG, 512>>>(gids, Wc, bc, out);
}

// round 16
// speedup vs baseline: 1.0179x; 1.0179x over previous
#include <cuda_runtime.h>
#include <cuda_fp16.h>
#include <cstdint>

#define NN   100000
#define EE   1000000
#define RR   4
#define GG   256
#define DHH  128
#define NCC  10
#define KK   (RR*DHH)   // 512
#define SB   98         // ceil(NN/1024)

// ---------------- scratch ----------------
__device__ __half    g_f16[(size_t)NN*DHH];
__device__ __half    g_h0h[(size_t)NN*DHH];
__device__ __half    g_h1h[(size_t)NN*DHH];
__device__ __half    g_aggh[(size_t)(NN+256)*KK];    // pad rows stay zero (never written)
__device__ unsigned  g_wt[3*DHH*256];                // per-layer W^T pair-packed half2
__device__ int       g_deg_out[RR*NN];
__device__ int       g_deg_in [RR*NN];
__device__ float     g_rno[RR*NN];
__device__ float     g_rni[RR*NN];
__device__ int       g_rowptr[RR*(NN+1)];
__device__ int       g_cursor[RR*NN];
__device__ unsigned  g_pcsr[(size_t)RR*EE];          // packed (src<<15)|(fp16 rno sans sign)
__device__ int       g_bsum[RR*SB];

// ---------------- conversions + degree zeroing (one kernel, runs first) ----------------
__global__ void conv_fw_k(const float* __restrict__ f, const float* __restrict__ W0,
                          const float* __restrict__ Wl) {
    int i = blockIdx.x * blockDim.x + threadIdx.x;
    if (i < NN*DHH/2) {
        float2 v = ((const float2*)f)[i];
        ((__half2*)g_f16)[i] = __floats2half2_rn(v.x, v.y);
    }
    if (i < 3*DHH*256) {
        int l = i / (DHH*256);
        int rem = i - l*DHH*256;
        int col = rem >> 8;
        int p = rem & 255;
        const float* src = (l == 0) ? W0 : Wl + (size_t)(l-1)*KK*DHH;
        __half2 hv = __floats2half2_rn(src[(size_t)(2*p)*DHH + col],
                                       src[(size_t)(2*p+1)*DHH + col]);
        g_wt[i] = *reinterpret_cast<unsigned*>(&hv);
    }
    if (i < RR*NN) { g_deg_out[i] = 0; g_deg_in[i] = 0; }
}

// ---------------- preprocessing ----------------
__global__ void count_deg_k(const int* __restrict__ edges) {
    int i = blockIdx.x * blockDim.x + threadIdx.x;
    if (i >= RR*EE/4) return;
    int r = i / (EE/4), q = i - r*(EE/4);
    int4 s = *(const int4*)(edges + (size_t)r*2*EE + q*4);
    int4 d = *(const int4*)(edges + (size_t)r*2*EE + EE + q*4);
    int* dout = g_deg_out + r*NN;
    int* din  = g_deg_in  + r*NN;
    atomicAdd(&dout[s.x], 1); atomicAdd(&dout[s.y], 1);
    atomicAdd(&dout[s.z], 1); atomicAdd(&dout[s.w], 1);
    atomicAdd(&din[d.x], 1);  atomicAdd(&din[d.y], 1);
    atomicAdd(&din[d.z], 1);  atomicAdd(&din[d.w], 1);
}

// block-local exclusive scan via warp shuffles; emits per-block sums
__global__ void scan1_k() {
    __shared__ int wsum[32];
    int r = blockIdx.y, b = blockIdx.x, t = threadIdx.x;
    int wp = t >> 5, lane = t & 31;
    int i = b * 1024 + t;
    int v = (i < NN) ? g_deg_in[r*NN + i] : 0;

    int s = v;
    #pragma unroll
    for (int o = 1; o < 32; o <<= 1) {
        int x = __shfl_up_sync(0xFFFFFFFFu, s, o);
        if (lane >= o) s += x;
    }
    if (lane == 31) wsum[wp] = s;
    __syncthreads();
    if (wp == 0) {
        int ws = wsum[lane];
        #pragma unroll
        for (int o = 1; o < 32; o <<= 1) {
            int x = __shfl_up_sync(0xFFFFFFFFu, ws, o);
            if (lane >= o) ws += x;
        }
        wsum[lane] = ws;
    }
    __syncthreads();

    int base = (wp > 0) ? wsum[wp - 1] : 0;
    int excl = base + s - v;
    if (i < NN) g_rowptr[r*(NN+1) + i] = excl;
    if (t == 1023) g_bsum[r*SB + b] = wsum[31];
}

// warp per relation: shuffle-scan the 98 block sums
__global__ void scan2_k() {
    int r = threadIdx.x >> 5, lane = threadIdx.x & 31;
    if (r >= RR) return;
    int run = 0;
    for (int c = 0; c < SB; c += 32) {
        int idx = c + lane;
        int v = (idx < SB) ? g_bsum[r*SB + idx] : 0;
        int s = v;
        #pragma unroll
        for (int o = 1; o < 32; o <<= 1) {
            int x = __shfl_up_sync(0xFFFFFFFFu, s, o);
            if (lane >= o) s += x;
        }
        if (idx < SB) g_bsum[r*SB + idx] = run + s - v;
        run += __shfl_sync(0xFFFFFFFFu, s, 31);
    }
    if (lane == 0) g_rowptr[r*(NN+1) + NN] = run;
}

// block offsets -> rowptr/cursor; fused degree-norm computation
__global__ void scan3_k() {
    int i = blockIdx.x * blockDim.x + threadIdx.x;
    if (i >= RR*NN) return;
    int r = i / NN, n = i - r*NN;
    int off = g_bsum[r*SB + (n >> 10)];
    int v = g_rowptr[r*(NN+1) + n] + off;
    g_rowptr[r*(NN+1) + n] = v;
    g_cursor[r*NN + n] = v;
    g_rno[i] = rsqrtf(fmaxf((float)g_deg_out[i], 1.0f));
    g_rni[i] = rsqrtf(fmaxf((float)g_deg_in [i], 1.0f));
}

__global__ void fill_k(const int* __restrict__ edges) {
    int i = blockIdx.x * blockDim.x + threadIdx.x;
    if (i >= RR*EE/4) return;
    int r = i / (EE/4), q = i - r*(EE/4);
    int4 s4 = *(const int4*)(edges + (size_t)r*2*EE + q*4);
    int4 d4 = *(const int4*)(edges + (size_t)r*2*EE + EE + q*4);
    const float* rno = g_rno + r*NN;
    int* cur = g_cursor + r*NN;
    unsigned* pc = g_pcsr + (size_t)r*EE;
    #pragma unroll
    for (int j = 0; j < 4; j++) {
        int src = (j == 0) ? s4.x : (j == 1) ? s4.y : (j == 2) ? s4.z : s4.w;
        int dst = (j == 0) ? d4.x : (j == 1) ? d4.y : (j == 2) ? d4.z : d4.w;
        float w = rno[src];
        unsigned short hb = __half_as_ushort(__float2half_rn(w));  // sign bit = 0
        unsigned ent = ((unsigned)src << 15) | (unsigned)(hb & 0x7FFF);
        int pos = atomicAdd(&cur[dst], 1);
        pc[pos] = ent;
    }
}

// ---------------- aggregation (proven): warp per (r,dst), 2 edges split ----------------
__global__ void __launch_bounds__(256) agg_k(int sel) {
    const __half* hin = (sel == 0) ? g_f16 : (sel == 1 ? g_h0h : g_h1h);
    int w = (blockIdx.x * blockDim.x + threadIdx.x) >> 5;
    if (w >= RR*NN) return;
    int lane = threadIdx.x & 31;
    int half = lane >> 4;
    int hl   = lane & 15;
    int r = w / NN, n = w - r*NN;
    int e0 = g_rowptr[r*(NN+1) + n];
    int e1 = g_rowptr[r*(NN+1) + n + 1];
    const unsigned* pc = g_pcsr + (size_t)r*EE;

    float a0=0.f,a1=0.f,a2=0.f,a3=0.f,a4=0.f,a5=0.f,a6=0.f,a7=0.f;
    for (int e = e0 + half; e < e1; e += 2) {
        unsigned ent = __ldg(pc + e);
        int s = ent >> 15;
        float wgt = __half2float(__ushort_as_half((unsigned short)(ent & 0x7FFF)));
        uint4 v = __ldg((const uint4*)(hin + (size_t)s*DHH) + hl);
        float2 f0 = __half22float2(*reinterpret_cast<__half2*>(&v.x));
        float2 f1 = __half22float2(*reinterpret_cast<__half2*>(&v.y));
        float2 f2 = __half22float2(*reinterpret_cast<__half2*>(&v.z));
        float2 f3 = __half22float2(*reinterpret_cast<__half2*>(&v.w));
        a0 = fmaf(wgt, f0.x, a0); a1 = fmaf(wgt, f0.y, a1);
        a2 = fmaf(wgt, f1.x, a2); a3 = fmaf(wgt, f1.y, a3);
        a4 = fmaf(wgt, f2.x, a4); a5 = fmaf(wgt, f2.y, a5);
        a6 = fmaf(wgt, f3.x, a6); a7 = fmaf(wgt, f3.y, a7);
    }
    a0 += __shfl_down_sync(0xFFFFFFFFu, a0, 16);
    a1 += __shfl_down_sync(0xFFFFFFFFu, a1, 16);
    a2 += __shfl_down_sync(0xFFFFFFFFu, a2, 16);
    a3 += __shfl_down_sync(0xFFFFFFFFu, a3, 16);
    a4 += __shfl_down_sync(0xFFFFFFFFu, a4, 16);
    a5 += __shfl_down_sync(0xFFFFFFFFu, a5, 16);
    a6 += __shfl_down_sync(0xFFFFFFFFu, a6, 16);
    a7 += __shfl_down_sync(0xFFFFFFFFu, a7, 16);

    if (half == 0) {
        float ri = g_rni[r*NN + n];
        __half2 p0 = __floats2half2_rn(ri*a0, ri*a1);
        __half2 p1 = __floats2half2_rn(ri*a2, ri*a3);
        __half2 p2 = __floats2half2_rn(ri*a4, ri*a5);
        __half2 p3 = __floats2half2_rn(ri*a6, ri*a7);
        uint4 o;
        o.x = *reinterpret_cast<unsigned*>(&p0);
        o.y = *reinterpret_cast<unsigned*>(&p1);
        o.z = *reinterpret_cast<unsigned*>(&p2);
        o.w = *reinterpret_cast<unsigned*>(&p3);
        *((uint4*)(g_aggh + (size_t)n*KK + r*DHH) + hl) = o;
    }
}

// ---------------- fp16 tensor-core GEMM: BM=128, 3-stage cp.async pipeline ----------------
__device__ __forceinline__ void mma_f16(float* c, const unsigned* a, const unsigned* b) {
    asm volatile(
        "mma.sync.aligned.m16n8k16.row.col.f32.f16.f16.f32 "
        "{%0,%1,%2,%3}, {%4,%5,%6,%7}, {%8,%9}, {%0,%1,%2,%3};"
        : "+f"(c[0]), "+f"(c[1]), "+f"(c[2]), "+f"(c[3])
        : "r"(a[0]), "r"(a[1]), "r"(a[2]), "r"(a[3]), "r"(b[0]), "r"(b[1]));
}

// BM=128, BN=128, BK=16, 256 threads, 8 warps 2(m)x4(n), warp tile 64x32
__global__ void __launch_bounds__(256) gemm_tc_k(int layer, const float* __restrict__ Bv,
                                                 int outsel) {
    __shared__ unsigned As[3][128][12];
    __shared__ unsigned Bs[3][128][12];

    __half* O = (outsel == 0) ? g_h0h : g_h1h;
    const __half* A = g_aggh;
    const unsigned* Wt = g_wt + (size_t)layer*DHH*256;

    int tid = threadIdx.x;
    int rb = blockIdx.x * 128;
    int wid = tid >> 5, lane = tid & 31;
    int wm = wid & 1, wn = wid >> 1;
    int g = lane >> 2, t = lane & 3;

    float acc[4][4][4];
    #pragma unroll
    for (int mt = 0; mt < 4; mt++)
        #pragma unroll
        for (int nt = 0; nt < 4; nt++)
            #pragma unroll
            for (int j = 0; j < 4; j++) acc[mt][nt][j] = 0.f;

    auto issue = [&](int kt, int buf) {
        #pragma unroll
        for (int p = 0; p < 2; p++) {
            int idx = tid + p*256;
            int row = idx >> 2, q = idx & 3;
            const __half* ga = A + (size_t)(rb + row)*KK + kt*16 + q*4;  // pad rows are zero
            unsigned sA = (unsigned)__cvta_generic_to_shared(&As[buf][row][2*q]);
            asm volatile("cp.async.ca.shared.global [%0], [%1], 8;" :: "r"(sA), "l"(ga));
            const unsigned* gb = Wt + (size_t)row*256 + kt*8 + q*2;
            unsigned sB = (unsigned)__cvta_generic_to_shared(&Bs[buf][row][2*q]);
            asm volatile("cp.async.ca.shared.global [%0], [%1], 8;" :: "r"(sB), "l"(gb));
        }
        asm volatile("cp.async.commit_group;");
    };

    issue(0, 0);
    issue(1, 1);

    for (int kt = 0; kt < 32; kt++) {
        int cur = kt % 3;
        if (kt < 31) asm volatile("cp.async.wait_group 1;");  // group kt arrived
        else         asm volatile("cp.async.wait_group 0;");
        __syncthreads();   // all warps done with compute(kt-1) -> buf (kt+2)%3 reusable
        if (kt + 2 < 32) issue(kt + 2, (kt + 2) % 3);

        unsigned af[4][4], bf[4][2];
        #pragma unroll
        for (int mt = 0; mt < 4; mt++) {
            int r0 = wm*64 + mt*16 + g;
            af[mt][0] = As[cur][r0    ][t];
            af[mt][1] = As[cur][r0 + 8][t];
            af[mt][2] = As[cur][r0    ][t + 4];
            af[mt][3] = As[cur][r0 + 8][t + 4];
        }
        #pragma unroll
        for (int nt = 0; nt < 4; nt++) {
            int c0 = wn*32 + nt*8 + g;
            bf[nt][0] = Bs[cur][c0][t];
            bf[nt][1] = Bs[cur][c0][t + 4];
        }
        #pragma unroll
        for (int mt = 0; mt < 4; mt++)
            #pragma unroll
            for (int nt = 0; nt < 4; nt++)
                mma_f16(acc[mt][nt], af[mt], bf[nt]);
    }

    float bias[4][2];
    #pragma unroll
    for (int nt = 0; nt < 4; nt++) {
        int c0 = wn*32 + nt*8 + 2*t;
        #pragma unroll
        for (int j = 0; j < 2; j++) {
            float s = 0.f;
            #pragma unroll
            for (int r = 0; r < RR; r++) s += Bv[r*DHH + c0 + j];
            bias[nt][j] = s;
        }
    }
    #pragma unroll
    for (int mt = 0; mt < 4; mt++) {
        int r0 = rb + wm*64 + mt*16 + g;
        #pragma unroll
        for (int nt = 0; nt < 4; nt++) {
            int c = wn*32 + nt*8 + 2*t;
            if (r0 < NN) {
                *(__half2*)(O + (size_t)r0*DHH + c) =
                    __floats2half2_rn(fmaxf(acc[mt][nt][0] + bias[nt][0], 0.f),
                                      fmaxf(acc[mt][nt][1] + bias[nt][1], 0.f));
            }
            if (r0 + 8 < NN) {
                *(__half2*)(O + (size_t)(r0+8)*DHH + c) =
                    __floats2half2_rn(fmaxf(acc[mt][nt][2] + bias[nt][0], 0.f),
                                      fmaxf(acc[mt][nt][3] + bias[nt][1], 0.f));
            }
        }
    }
}

// ---------------- pooling + classifier (binary-search bounds, fused) ----------------
__global__ void poolcls_k(const int* __restrict__ gid, const float* __restrict__ Wc,
                          const float* __restrict__ bc, float* __restrict__ out) {
    __shared__ float sh[3*DHH];
    __shared__ float pooled[DHH];
    __shared__ int ab[2];
    int g = blockIdx.x;
    if (threadIdx.x < 2) {
        int target = g + threadIdx.x;
        int lo = 0, hi = NN;
        while (lo < hi) {
            int mid = (lo + hi) >> 1;
            if (gid[mid] < target) lo = mid + 1; else hi = mid;
        }
        ab[threadIdx.x] = lo;
    }
    __syncthreads();
    int a = ab[0], b = ab[1];
    int j  = threadIdx.x & 127;
    int rl = threadIdx.x >> 7;
    float s = 0.f;
    for (int n = a + rl; n < b; n += 4)
        s += __half2float(g_h0h[(size_t)n*DHH + j]);
    if (rl > 0) sh[(rl-1)*DHH + j] = s;
    __syncthreads();
    if (rl == 0) {
        s += sh[j] + sh[DHH + j] + sh[2*DHH + j];
        float c = fmaxf((float)(b - a), 1.0f);
        pooled[j] = s / c;
    }
    __syncthreads();
    int wid = threadIdx.x >> 5, lane = threadIdx.x & 31;
    if (wid < NCC) {
        float acc = 0.f;
        #pragma unroll
        for (int k = lane; k < DHH; k += 32)
            acc = fmaf(pooled[k], Wc[k*NCC + wid], acc);
        #pragma unroll
        for (int o = 16; o > 0; o >>= 1)
            acc += __shfl_down_sync(0xFFFFFFFFu, acc, o);
        if (lane == 0) out[g*NCC + wid] = acc + bc[wid];
    }
}

// ---------------- launch ----------------
extern "C" void kernel_launch(void* const* d_in, const int* in_sizes, int n_in,
                              void* d_out, int out_size) {
    const float* features = (const float*)d_in[0];
    const int*   edges    = (const int*)  d_in[1];
    const int*   gids     = (const int*)  d_in[2];
    const float* W0       = (const float*)d_in[3];
    const float* b0       = (const float*)d_in[4];
    const float* Wl       = (const float*)d_in[5];
    const float* bl       = (const float*)d_in[6];
    const float* Wc       = (const float*)d_in[7];
    const float* bc       = (const float*)d_in[8];
    float* out = (float*)d_out;

    conv_fw_k  <<<(NN*DHH/2 + 255)/256, 256>>>(features, W0, Wl);   // also zeros degrees
    count_deg_k<<<(RR*EE/4 + 255)/256, 256>>>(edges);
    scan1_k    <<<dim3(SB, RR), 1024>>>();
    scan2_k    <<<1, 128>>>();
    scan3_k    <<<(RR*NN + 255)/256, 256>>>();
    fill_k     <<<(RR*EE/4 + 255)/256, 256>>>(edges);

    const int AGG_BLOCKS  = (RR*NN*32 + 255)/256;
    const int GEMM_BLOCKS = (NN + 127)/128;

    agg_k    <<<AGG_BLOCKS, 256>>>(0);
    gemm_tc_k<<<GEMM_BLOCKS, 256>>>(0, b0, 0);
    agg_k    <<<AGG_BLOCKS, 256>>>(1);
    gemm_tc_k<<<GEMM_BLOCKS, 256>>>(1, bl, 1);
    agg_k    <<<AGG_BLOCKS, 256>>>(2);
    gemm_tc_k<<<GEMM_BLOCKS, 256>>>(2, bl + RR*DHH, 0);

    poolcls_k<<<GG, 512>>>(gids, Wc, bc, out);
}

// round 17
// speedup vs baseline: 1.0407x; 1.0225x over previous
#include <cuda_runtime.h>
#include <cuda_fp16.h>
#include <cstdint>

#define NN   100000
#define EE   1000000
#define RR   4
#define GG   256
#define DHH  128
#define NCC  10
#define KK   (RR*DHH)   // 512
#define SB   98         // ceil(NN/1024)

// ---------------- scratch ----------------
__device__ __half    g_f16[(size_t)NN*DHH];
__device__ __half    g_h0h[(size_t)NN*DHH];
__device__ __half    g_h1h[(size_t)NN*DHH];
__device__ __half    g_aggh[(size_t)(NN+256)*KK];    // pad rows stay zero (never written)
__device__ unsigned  g_wt[3*DHH*256];                // per-layer W^T pair-packed half2
__device__ int       g_deg_out[RR*NN];
__device__ int       g_deg_in [RR*NN];
__device__ float     g_rno[RR*NN];
__device__ float     g_rni[RR*NN];
__device__ int       g_rowptr[RR*(NN+1)];
__device__ int       g_cursor[RR*NN];
__device__ unsigned  g_pcsr[(size_t)RR*EE];          // packed (src<<15)|(fp16 rno sans sign)
__device__ int       g_bsum[RR*SB];

// ---------------- conversions + degree zeroing (one kernel, runs first) ----------------
__global__ void conv_fw_k(const float* __restrict__ f, const float* __restrict__ W0,
                          const float* __restrict__ Wl) {
    int i = blockIdx.x * blockDim.x + threadIdx.x;
    if (i < NN*DHH/2) {
        float2 v = ((const float2*)f)[i];
        ((__half2*)g_f16)[i] = __floats2half2_rn(v.x, v.y);
    }
    if (i < 3*DHH*256) {
        int l = i / (DHH*256);
        int rem = i - l*DHH*256;
        int col = rem >> 8;
        int p = rem & 255;
        const float* src = (l == 0) ? W0 : Wl + (size_t)(l-1)*KK*DHH;
        __half2 hv = __floats2half2_rn(src[(size_t)(2*p)*DHH + col],
                                       src[(size_t)(2*p+1)*DHH + col]);
        g_wt[i] = *reinterpret_cast<unsigned*>(&hv);
    }
    if (i < RR*NN) { g_deg_out[i] = 0; g_deg_in[i] = 0; }
}

// ---------------- preprocessing ----------------
__global__ void count_deg_k(const int* __restrict__ edges) {
    int i = blockIdx.x * blockDim.x + threadIdx.x;
    if (i >= RR*EE/4) return;
    int r = i / (EE/4), q = i - r*(EE/4);
    int4 s = *(const int4*)(edges + (size_t)r*2*EE + q*4);
    int4 d = *(const int4*)(edges + (size_t)r*2*EE + EE + q*4);
    int* dout = g_deg_out + r*NN;
    int* din  = g_deg_in  + r*NN;
    atomicAdd(&dout[s.x], 1); atomicAdd(&dout[s.y], 1);
    atomicAdd(&dout[s.z], 1); atomicAdd(&dout[s.w], 1);
    atomicAdd(&din[d.x], 1);  atomicAdd(&din[d.y], 1);
    atomicAdd(&din[d.z], 1);  atomicAdd(&din[d.w], 1);
}

// block-local exclusive scan via warp shuffles; emits per-block sums
__global__ void scan1_k() {
    __shared__ int wsum[32];
    int r = blockIdx.y, b = blockIdx.x, t = threadIdx.x;
    int wp = t >> 5, lane = t & 31;
    int i = b * 1024 + t;
    int v = (i < NN) ? g_deg_in[r*NN + i] : 0;

    int s = v;
    #pragma unroll
    for (int o = 1; o < 32; o <<= 1) {
        int x = __shfl_up_sync(0xFFFFFFFFu, s, o);
        if (lane >= o) s += x;
    }
    if (lane == 31) wsum[wp] = s;
    __syncthreads();
    if (wp == 0) {
        int ws = wsum[lane];
        #pragma unroll
        for (int o = 1; o < 32; o <<= 1) {
            int x = __shfl_up_sync(0xFFFFFFFFu, ws, o);
            if (lane >= o) ws += x;
        }
        wsum[lane] = ws;
    }
    __syncthreads();

    int base = (wp > 0) ? wsum[wp - 1] : 0;
    int excl = base + s - v;
    if (i < NN) g_rowptr[r*(NN+1) + i] = excl;
    if (t == 1023) g_bsum[r*SB + b] = wsum[31];
}

// warp per relation: shuffle-scan the 98 block sums
__global__ void scan2_k() {
    int r = threadIdx.x >> 5, lane = threadIdx.x & 31;
    if (r >= RR) return;
    int run = 0;
    for (int c = 0; c < SB; c += 32) {
        int idx = c + lane;
        int v = (idx < SB) ? g_bsum[r*SB + idx] : 0;
        int s = v;
        #pragma unroll
        for (int o = 1; o < 32; o <<= 1) {
            int x = __shfl_up_sync(0xFFFFFFFFu, s, o);
            if (lane >= o) s += x;
        }
        if (idx < SB) g_bsum[r*SB + idx] = run + s - v;
        run += __shfl_sync(0xFFFFFFFFu, s, 31);
    }
    if (lane == 0) g_rowptr[r*(NN+1) + NN] = run;
}

// block offsets -> rowptr/cursor; fused degree-norm computation
__global__ void scan3_k() {
    int i = blockIdx.x * blockDim.x + threadIdx.x;
    if (i >= RR*NN) return;
    int r = i / NN, n = i - r*NN;
    int off = g_bsum[r*SB + (n >> 10)];
    int v = g_rowptr[r*(NN+1) + n] + off;
    g_rowptr[r*(NN+1) + n] = v;
    g_cursor[r*NN + n] = v;
    g_rno[i] = rsqrtf(fmaxf((float)g_deg_out[i], 1.0f));
    g_rni[i] = rsqrtf(fmaxf((float)g_deg_in [i], 1.0f));
}

__global__ void fill_k(const int* __restrict__ edges) {
    int i = blockIdx.x * blockDim.x + threadIdx.x;
    if (i >= RR*EE/4) return;
    int r = i / (EE/4), q = i - r*(EE/4);
    int4 s4 = *(const int4*)(edges + (size_t)r*2*EE + q*4);
    int4 d4 = *(const int4*)(edges + (size_t)r*2*EE + EE + q*4);
    const float* rno = g_rno + r*NN;
    int* cur = g_cursor + r*NN;
    unsigned* pc = g_pcsr + (size_t)r*EE;
    #pragma unroll
    for (int j = 0; j < 4; j++) {
        int src = (j == 0) ? s4.x : (j == 1) ? s4.y : (j == 2) ? s4.z : s4.w;
        int dst = (j == 0) ? d4.x : (j == 1) ? d4.y : (j == 2) ? d4.z : d4.w;
        float w = rno[src];
        unsigned short hb = __half_as_ushort(__float2half_rn(w));  // sign bit = 0
        unsigned ent = ((unsigned)src << 15) | (unsigned)(hb & 0x7FFF);
        int pos = atomicAdd(&cur[dst], 1);
        pc[pos] = ent;
    }
}

// ---------------- aggregation (proven): warp per (r,dst), 2 edges split ----------------
__global__ void __launch_bounds__(256) agg_k(int sel) {
    const __half* hin = (sel == 0) ? g_f16 : (sel == 1 ? g_h0h : g_h1h);
    int w = (blockIdx.x * blockDim.x + threadIdx.x) >> 5;
    if (w >= RR*NN) return;
    int lane = threadIdx.x & 31;
    int half = lane >> 4;
    int hl   = lane & 15;
    int r = w / NN, n = w - r*NN;
    int e0 = g_rowptr[r*(NN+1) + n];
    int e1 = g_rowptr[r*(NN+1) + n + 1];
    const unsigned* pc = g_pcsr + (size_t)r*EE;

    float a0=0.f,a1=0.f,a2=0.f,a3=0.f,a4=0.f,a5=0.f,a6=0.f,a7=0.f;
    for (int e = e0 + half; e < e1; e += 2) {
        unsigned ent = __ldg(pc + e);
        int s = ent >> 15;
        float wgt = __half2float(__ushort_as_half((unsigned short)(ent & 0x7FFF)));
        uint4 v = __ldg((const uint4*)(hin + (size_t)s*DHH) + hl);
        float2 f0 = __half22float2(*reinterpret_cast<__half2*>(&v.x));
        float2 f1 = __half22float2(*reinterpret_cast<__half2*>(&v.y));
        float2 f2 = __half22float2(*reinterpret_cast<__half2*>(&v.z));
        float2 f3 = __half22float2(*reinterpret_cast<__half2*>(&v.w));
        a0 = fmaf(wgt, f0.x, a0); a1 = fmaf(wgt, f0.y, a1);
        a2 = fmaf(wgt, f1.x, a2); a3 = fmaf(wgt, f1.y, a3);
        a4 = fmaf(wgt, f2.x, a4); a5 = fmaf(wgt, f2.y, a5);
        a6 = fmaf(wgt, f3.x, a6); a7 = fmaf(wgt, f3.y, a7);
    }
    a0 += __shfl_down_sync(0xFFFFFFFFu, a0, 16);
    a1 += __shfl_down_sync(0xFFFFFFFFu, a1, 16);
    a2 += __shfl_down_sync(0xFFFFFFFFu, a2, 16);
    a3 += __shfl_down_sync(0xFFFFFFFFu, a3, 16);
    a4 += __shfl_down_sync(0xFFFFFFFFu, a4, 16);
    a5 += __shfl_down_sync(0xFFFFFFFFu, a5, 16);
    a6 += __shfl_down_sync(0xFFFFFFFFu, a6, 16);
    a7 += __shfl_down_sync(0xFFFFFFFFu, a7, 16);

    if (half == 0) {
        float ri = g_rni[r*NN + n];
        __half2 p0 = __floats2half2_rn(ri*a0, ri*a1);
        __half2 p1 = __floats2half2_rn(ri*a2, ri*a3);
        __half2 p2 = __floats2half2_rn(ri*a4, ri*a5);
        __half2 p3 = __floats2half2_rn(ri*a6, ri*a7);
        uint4 o;
        o.x = *reinterpret_cast<unsigned*>(&p0);
        o.y = *reinterpret_cast<unsigned*>(&p1);
        o.z = *reinterpret_cast<unsigned*>(&p2);
        o.w = *reinterpret_cast<unsigned*>(&p3);
        *((uint4*)(g_aggh + (size_t)n*KK + r*DHH) + hl) = o;
    }
}

// ---------------- fp16 tensor-core GEMM: cp.async 2-group pipeline (proven optimum) ----------
__device__ __forceinline__ void mma_f16(float* c, const unsigned* a, const unsigned* b) {
    asm volatile(
        "mma.sync.aligned.m16n8k16.row.col.f32.f16.f16.f32 "
        "{%0,%1,%2,%3}, {%4,%5,%6,%7}, {%8,%9}, {%0,%1,%2,%3};"
        : "+f"(c[0]), "+f"(c[1]), "+f"(c[2]), "+f"(c[3])
        : "r"(a[0]), "r"(a[1]), "r"(a[2]), "r"(a[3]), "r"(b[0]), "r"(b[1]));
}

// BM=128, BN=128, BK=16, 256 threads, 8 warps 2(m)x4(n), warp tile 64x32
__global__ void __launch_bounds__(256) gemm_tc_k(int layer, const float* __restrict__ Bv,
                                                 int outsel) {
    __shared__ unsigned As[2][128][12];
    __shared__ unsigned Bs[2][128][12];

    __half* O = (outsel == 0) ? g_h0h : g_h1h;
    const __half* A = g_aggh;
    const unsigned* Wt = g_wt + (size_t)layer*DHH*256;

    int tid = threadIdx.x;
    int rb = blockIdx.x * 128;
    int wid = tid >> 5, lane = tid & 31;
    int wm = wid & 1, wn = wid >> 1;
    int g = lane >> 2, t = lane & 3;

    float acc[4][4][4];
    #pragma unroll
    for (int mt = 0; mt < 4; mt++)
        #pragma unroll
        for (int nt = 0; nt < 4; nt++)
            #pragma unroll
            for (int j = 0; j < 4; j++) acc[mt][nt][j] = 0.f;

    auto issue = [&](int kt, int buf) {
        #pragma unroll
        for (int p = 0; p < 2; p++) {
            int idx = tid + p*256;
            int row = idx >> 2, q = idx & 3;
            const __half* ga = A + (size_t)(rb + row)*KK + kt*16 + q*4;  // pad rows are zero
            unsigned sA = (unsigned)__cvta_generic_to_shared(&As[buf][row][2*q]);
            asm volatile("cp.async.ca.shared.global [%0], [%1], 8;" :: "r"(sA), "l"(ga));
            const unsigned* gb = Wt + (size_t)row*256 + kt*8 + q*2;
            unsigned sB = (unsigned)__cvta_generic_to_shared(&Bs[buf][row][2*q]);
            asm volatile("cp.async.ca.shared.global [%0], [%1], 8;" :: "r"(sB), "l"(gb));
        }
        asm volatile("cp.async.commit_group;");
    };

    issue(0, 0);

    for (int kt = 0; kt < 32; kt++) {
        int cur = kt & 1;
        if (kt < 31) {
            issue(kt + 1, cur ^ 1);                    // overlaps compute(kt)
            asm volatile("cp.async.wait_group 1;");    // group kt done; kt+1 in flight
        } else {
            asm volatile("cp.async.wait_group 0;");
        }
        __syncthreads();

        unsigned af[4][4], bf[4][2];
        #pragma unroll
        for (int mt = 0; mt < 4; mt++) {
            int r0 = wm*64 + mt*16 + g;
            af[mt][0] = As[cur][r0    ][t];
            af[mt][1] = As[cur][r0 + 8][t];
            af[mt][2] = As[cur][r0    ][t + 4];
            af[mt][3] = As[cur][r0 + 8][t + 4];
        }
        #pragma unroll
        for (int nt = 0; nt < 4; nt++) {
            int c0 = wn*32 + nt*8 + g;
            bf[nt][0] = Bs[cur][c0][t];
            bf[nt][1] = Bs[cur][c0][t + 4];
        }
        #pragma unroll
        for (int mt = 0; mt < 4; mt++)
            #pragma unroll
            for (int nt = 0; nt < 4; nt++)
                mma_f16(acc[mt][nt], af[mt], bf[nt]);

        __syncthreads();   // frees buf cur for issue(kt+2)
    }

    float bias[4][2];
    #pragma unroll
    for (int nt = 0; nt < 4; nt++) {
        int c0 = wn*32 + nt*8 + 2*t;
        #pragma unroll
        for (int j = 0; j < 2; j++) {
            float s = 0.f;
            #pragma unroll
            for (int r = 0; r < RR; r++) s += Bv[r*DHH + c0 + j];
            bias[nt][j] = s;
        }
    }
    #pragma unroll
    for (int mt = 0; mt < 4; mt++) {
        int r0 = rb + wm*64 + mt*16 + g;
        #pragma unroll
        for (int nt = 0; nt < 4; nt++) {
            int c = wn*32 + nt*8 + 2*t;
            if (r0 < NN) {
                *(__half2*)(O + (size_t)r0*DHH + c) =
                    __floats2half2_rn(fmaxf(acc[mt][nt][0] + bias[nt][0], 0.f),
                                      fmaxf(acc[mt][nt][1] + bias[nt][1], 0.f));
            }
            if (r0 + 8 < NN) {
                *(__half2*)(O + (size_t)(r0+8)*DHH + c) =
                    __floats2half2_rn(fmaxf(acc[mt][nt][2] + bias[nt][0], 0.f),
                                      fmaxf(acc[mt][nt][3] + bias[nt][1], 0.f));
            }
        }
    }
}

// ---------------- pooling + classifier (binary-search bounds, fused) ----------------
__global__ void poolcls_k(const int* __restrict__ gid, const float* __restrict__ Wc,
                          const float* __restrict__ bc, float* __restrict__ out) {
    __shared__ float sh[3*DHH];
    __shared__ float pooled[DHH];
    __shared__ int ab[2];
    int g = blockIdx.x;
    if (threadIdx.x < 2) {
        int target = g + threadIdx.x;
        int lo = 0, hi = NN;
        while (lo < hi) {
            int mid = (lo + hi) >> 1;
            if (gid[mid] < target) lo = mid + 1; else hi = mid;
        }
        ab[threadIdx.x] = lo;
    }
    __syncthreads();
    int a = ab[0], b = ab[1];
    int j  = threadIdx.x & 127;
    int rl = threadIdx.x >> 7;
    float s = 0.f;
    for (int n = a + rl; n < b; n += 4)
        s += __half2float(g_h0h[(size_t)n*DHH + j]);
    if (rl > 0) sh[(rl-1)*DHH + j] = s;
    __syncthreads();
    if (rl == 0) {
        s += sh[j] + sh[DHH + j] + sh[2*DHH + j];
        float c = fmaxf((float)(b - a), 1.0f);
        pooled[j] = s / c;
    }
    __syncthreads();
    int wid = threadIdx.x >> 5, lane = threadIdx.x & 31;
    if (wid < NCC) {
        float acc = 0.f;
        #pragma unroll
        for (int k = lane; k < DHH; k += 32)
            acc = fmaf(pooled[k], Wc[k*NCC + wid], acc);
        #pragma unroll
        for (int o = 16; o > 0; o >>= 1)
            acc += __shfl_down_sync(0xFFFFFFFFu, acc, o);
        if (lane == 0) out[g*NCC + wid] = acc + bc[wid];
    }
}

// ---------------- launch ----------------
extern "C" void kernel_launch(void* const* d_in, const int* in_sizes, int n_in,
                              void* d_out, int out_size) {
    const float* features = (const float*)d_in[0];
    const int*   edges    = (const int*)  d_in[1];
    const int*   gids     = (const int*)  d_in[2];
    const float* W0       = (const float*)d_in[3];
    const float* b0       = (const float*)d_in[4];
    const float* Wl       = (const float*)d_in[5];
    const float* bl       = (const float*)d_in[6];
    const float* Wc       = (const float*)d_in[7];
    const float* bc       = (const float*)d_in[8];
    float* out = (float*)d_out;

    conv_fw_k  <<<(NN*DHH/2 + 255)/256, 256>>>(features, W0, Wl);   // also zeros degrees
    count_deg_k<<<(RR*EE/4 + 255)/256, 256>>>(edges);
    scan1_k    <<<dim3(SB, RR), 1024>>>();
    scan2_k    <<<1, 128>>>();
    scan3_k    <<<(RR*NN + 255)/256, 256>>>();
    fill_k     <<<(RR*EE/4 + 255)/256, 256>>>(edges);

    const int AGG_BLOCKS  = (RR*NN*32 + 255)/256;
    const int GEMM_BLOCKS = (NN + 127)/128;

    agg_k    <<<AGG_BLOCKS, 256>>>(0);
    gemm_tc_k<<<GEMM_BLOCKS, 256>>>(0, b0, 0);
    agg_k    <<<AGG_BLOCKS, 256>>>(1);
    gemm_tc_k<<<GEMM_BLOCKS, 256>>>(1, bl, 1);
    agg_k    <<<AGG_BLOCKS, 256>>>(2);
    gemm_tc_k<<<GEMM_BLOCKS, 256>>>(2, bl + RR*DHH, 0);

    poolcls_k<<<GG, 512>>>(gids, Wc, bc, out);
}